// round 5
// baseline (speedup 1.0000x reference)
#include <cuda_runtime.h>
#include <cuda.h>
#include <cudaTypedefs.h>
#include <cstdint>

#define NE   8
#define DIM  2048
#define FFN  5632
#define NT   4096
#define NROWS 10240             // routed rows (<=8192) + per-expert 128-pad

#define BM   128
#define BN1  128                // gemm1 N tile
#define BN2  256                // gemm2 N tile
#define BK   32                 // k floats per stage = 128B = SW128 atom
#define KT1  (DIM/BK)           // 64
#define KT2  (FFN/BK)           // 176
#define ST   4

#define A_BYTES  (BM*128)       // 16384
#define B1_BYTES (BN1*128)      // 16384 (per matrix)
#define B2_BYTES (BN2*128)      // 32768

#define FULL_OFF(s)  (0  + 8*(s))
#define EMPTY_OFF(s) (64 + 8*(s))
#define SM1_STAGE (A_BYTES + 2*B1_BYTES)          // 49152
#define SM1_A(s)  (1024 + (s)*SM1_STAGE)
#define SM1_B1(s) (SM1_A(s) + A_BYTES)
#define SM1_B3(s) (SM1_B1(s) + B1_BYTES)
#define SM2_STAGE (A_BYTES + B2_BYTES)            // 49152
#define SM2_A(s)  (1024 + (s)*SM2_STAGE)
#define SM2_B(s)  (SM2_A(s) + A_BYTES)
#define SM_TOTAL  (1024 + ST*49152)               // 197632

// ---------------- device scratch (~390 MB total) ----------------
__device__ int   g_counts[NE];
__device__ int   g_base[NE];
__device__ int   g_slot_of[NT*NE];
__device__ float g_xp[(size_t)NROWS*DIM];        // permuted + RNE-rounded x
__device__ float g_h[(size_t)NROWS*FFN];         // RNE-rounded SwiGLU output
__device__ float g_y[(size_t)NROWS*DIM];

// ---------------- helpers ----------------
__device__ __forceinline__ uint32_t smem_u32(const void* p) {
    uint32_t a;
    asm("{ .reg .u64 t; cvta.to.shared.u64 t, %1; cvt.u32.u64 %0, t; }" : "=r"(a) : "l"(p));
    return a;
}
__device__ __forceinline__ bool elect_one() {
    uint32_t pred;
    asm volatile("{\n\t.reg .pred p;\n\telect.sync _|p, 0xFFFFFFFF;\n\tselp.b32 %0, 1, 0, p;\n\t}"
                 : "=r"(pred));
    return pred != 0;
}
#define MBAR_INIT(addr, cnt) \
    asm volatile("mbarrier.init.shared.b64 [%0], %1;" :: "r"((uint32_t)(addr)), "r"((uint32_t)(cnt)) : "memory")
#define MBAR_EXPECT_TX(addr, bytes) \
    asm volatile("mbarrier.arrive.expect_tx.shared.b64 _, [%0], %1;" :: "r"((uint32_t)(addr)), "r"((uint32_t)(bytes)) : "memory")
#define MBAR_ARRIVE(addr) \
    asm volatile("mbarrier.arrive.shared.b64 _, [%0];" :: "r"((uint32_t)(addr)) : "memory")
#define MBAR_WAIT(addr, ph) do { \
    asm volatile("{\n\t.reg .pred P1;\n\t" \
        "WAIT_%=:\n\t" \
        "mbarrier.try_wait.parity.acquire.cta.shared::cta.b64 P1, [%0], %1, 0x989680;\n\t" \
        "@P1 bra.uni DONE_%=;\n\t" \
        "bra.uni WAIT_%=;\n\t" \
        "DONE_%=:\n\t}" \
        :: "r"((uint32_t)(addr)), "r"((uint32_t)(ph)) : "memory"); \
} while (0)

__device__ __forceinline__ void tma2d(uint32_t dst, const CUtensorMap* m, int x, int y, uint32_t bar) {
    asm volatile(
        "cp.async.bulk.tensor.2d.shared::cta.global.tile.mbarrier::complete_tx::bytes "
        "[%0], [%1, {%2, %3}], [%4];"
        :: "r"(dst), "l"(m), "r"(x), "r"(y), "r"(bar) : "memory");
}
__device__ __forceinline__ void mma_tf32(float c[4], const uint32_t a[4], const uint32_t b[2]) {
    asm volatile(
        "mma.sync.aligned.m16n8k8.row.col.f32.tf32.tf32.f32 "
        "{%0,%1,%2,%3}, {%4,%5,%6,%7}, {%8,%9}, {%0,%1,%2,%3};\n"
        : "+f"(c[0]), "+f"(c[1]), "+f"(c[2]), "+f"(c[3])
        : "r"(a[0]), "r"(a[1]), "r"(a[2]), "r"(a[3]), "r"(b[0]), "r"(b[1]));
}
__device__ __forceinline__ uint32_t tf32_bits(float f) {
    uint32_t r; asm("cvt.rna.tf32.f32 %0, %1;" : "=r"(r) : "f"(f)); return r;
}
__device__ __forceinline__ float rnef(float f) { return __uint_as_float(tf32_bits(f)); }
__device__ __forceinline__ uint32_t lds_u32(uint32_t addr) {
    uint32_t v; asm volatile("ld.shared.b32 %0, [%1];" : "=r"(v) : "r"(addr)); return v;
}
__device__ __forceinline__ float lds_f32(uint32_t addr) {
    float v; asm volatile("ld.shared.f32 %0, [%1];" : "=f"(v) : "r"(addr)); return v;
}

// ---------------- routing: zero + warp-aggregated route + prefix, one CTA ----------------
__global__ void route_all_k(const int* __restrict__ map) {
    const int tid = threadIdx.x;           // 1024 threads
    const int lane = tid & 31;
    if (tid < NE) g_counts[tid] = 0;
    __syncthreads();
    const unsigned lt = (1u << lane) - 1u;
    for (int t = tid; t < NT; t += 1024) {
        #pragma unroll
        for (int e = 0; e < NE; e++) {
            int r = map[t*NE + e];
            unsigned msk = __ballot_sync(0xffffffffu, r != 0);
            int b = 0;
            if (lane == 0) b = atomicAdd(&g_counts[e], __popc(msk));
            b = __shfl_sync(0xffffffffu, b, 0);
            if (r) g_slot_of[t*NE + e] = b + __popc(msk & lt);
        }
    }
    __syncthreads();
    if (tid == 0) {
        int acc = 0;
        #pragma unroll
        for (int e = 0; e < NE; e++) { g_base[e] = acc; acc += (g_counts[e] + 127) & ~127; }
    }
}

__global__ void permute_round_k(const float* __restrict__ x, const int* __restrict__ map) {
    const int t = blockIdx.x, tid = threadIdx.x;
    const float4* xr = (const float4*)(x + (size_t)t*DIM);
    float4 a = xr[tid], b = xr[tid + 256];
    a.x = rnef(a.x); a.y = rnef(a.y); a.z = rnef(a.z); a.w = rnef(a.w);
    b.x = rnef(b.x); b.y = rnef(b.y); b.z = rnef(b.z); b.w = rnef(b.w);
    #pragma unroll
    for (int e = 0; e < NE; e++) {
        if (map[t*NE + e]) {
            int row = g_base[e] + g_slot_of[t*NE + e];
            float4* d = (float4*)(g_xp + (size_t)row*DIM);
            d[tid] = a; d[tid + 256] = b;
        }
    }
}

// ---------------- GEMM1: u=Xp@W1^T, v=Xp@W3^T, h=rne(silu(u)*v) ----------------
// 288 threads: 8 consumer warps (warp tile 64x32, 2M x 4N), warp 8 = TMA producer.
__global__ void __launch_bounds__(288, 1)
gemm1_k(const __grid_constant__ CUtensorMap a_map,
        const __grid_constant__ CUtensorMap b1_map,
        const __grid_constant__ CUtensorMap b3_map)
{
    const int e = blockIdx.z;
    const int cnt = g_counts[e];
    const int m0 = blockIdx.x * BM;
    if (m0 >= cnt) return;
    const int base = g_base[e];
    const int n0 = blockIdx.y * BN1;

    extern __shared__ __align__(1024) char smem[];
    const uint32_t sb = smem_u32(smem);
    const int tid = threadIdx.x, wid = tid >> 5, lane = tid & 31;

    if (tid == 0) {
        #pragma unroll
        for (int s = 0; s < ST; s++) { MBAR_INIT(sb+FULL_OFF(s), 1); MBAR_INIT(sb+EMPTY_OFF(s), 8); }
    }
    __syncthreads();

    if (wid == 8) {                 // ---- TMA producer ----
        int s = 0, ph = 1;
        #pragma unroll 1
        for (int kt = 0; kt < KT1; kt++) {
            MBAR_WAIT(sb+EMPTY_OFF(s), ph);
            if (elect_one()) {
                MBAR_EXPECT_TX(sb+FULL_OFF(s), SM1_STAGE);
                tma2d(sb+SM1_A(s),  &a_map,  kt*BK, base + m0,  sb+FULL_OFF(s));
                tma2d(sb+SM1_B1(s), &b1_map, kt*BK, e*FFN + n0, sb+FULL_OFF(s));
                tma2d(sb+SM1_B3(s), &b3_map, kt*BK, e*FFN + n0, sb+FULL_OFF(s));
            }
            if (++s == ST) { s = 0; ph ^= 1; }
        }
        return;
    }

    // ---- consumer: warp tile 64(M) x 32(N) ----
    const int wm = (wid & 1) * 64, wn = (wid >> 1) * 32;
    const int g = lane >> 2, tg = lane & 3;
    const uint32_t mk = (uint32_t)g << 4;               // SW128 swizzle (row&7 == g)

    uint32_t aRow[8], bRow[4], cofs[4][2];
    #pragma unroll
    for (int i = 0; i < 8; i++) aRow[i] = (uint32_t)(wm + g + i*8) * 128;
    #pragma unroll
    for (int i = 0; i < 4; i++) bRow[i] = (uint32_t)(wn + i*8 + g) * 128;
    #pragma unroll
    for (int kk = 0; kk < 4; kk++) {
        cofs[kk][0] = ((uint32_t)(kk*8 + tg)     * 4) ^ mk;
        cofs[kk][1] = ((uint32_t)(kk*8 + tg + 4) * 4) ^ mk;
    }

    float acc1[4][4][4] = {}, acc3[4][4][4] = {};
    int s = 0, ph = 0;
    #pragma unroll 1
    for (int kt = 0; kt < KT1; kt++) {
        MBAR_WAIT(sb+FULL_OFF(s), ph);
        const uint32_t At = sb + SM1_A(s), B1t = sb + SM1_B1(s), B3t = sb + SM1_B3(s);
        #pragma unroll
        for (int kk = 0; kk < 4; kk++) {
            uint32_t a[4][4];
            #pragma unroll
            for (int mi = 0; mi < 4; mi++) {
                a[mi][0] = lds_u32(At + aRow[2*mi]   + cofs[kk][0]);
                a[mi][1] = lds_u32(At + aRow[2*mi+1] + cofs[kk][0]);
                a[mi][2] = lds_u32(At + aRow[2*mi]   + cofs[kk][1]);
                a[mi][3] = lds_u32(At + aRow[2*mi+1] + cofs[kk][1]);
            }
            #pragma unroll
            for (int ni = 0; ni < 4; ni++) {
                uint32_t b1f[2], b3f[2];
                b1f[0] = tf32_bits(lds_f32(B1t + bRow[ni] + cofs[kk][0]));
                b1f[1] = tf32_bits(lds_f32(B1t + bRow[ni] + cofs[kk][1]));
                b3f[0] = tf32_bits(lds_f32(B3t + bRow[ni] + cofs[kk][0]));
                b3f[1] = tf32_bits(lds_f32(B3t + bRow[ni] + cofs[kk][1]));
                #pragma unroll
                for (int mi = 0; mi < 4; mi++) {
                    mma_tf32(acc1[mi][ni], a[mi], b1f);
                    mma_tf32(acc3[mi][ni], a[mi], b3f);
                }
            }
        }
        __syncwarp();
        if (lane == 0) MBAR_ARRIVE(sb+EMPTY_OFF(s));
        if (++s == ST) { s = 0; ph ^= 1; }
    }

    // epilogue: h = rne(silu(u)*v)  (rows >= cnt hold garbage, never read)
    #pragma unroll
    for (int mi = 0; mi < 4; mi++) {
        #pragma unroll
        for (int ni = 0; ni < 4; ni++) {
            int row = base + m0 + wm + mi*16 + g;
            int col = n0 + wn + ni*8 + tg*2;
            size_t o = (size_t)row*FFN + col;
            float u0 = acc1[mi][ni][0], u1 = acc1[mi][ni][1];
            float v0 = acc3[mi][ni][0], v1 = acc3[mi][ni][1];
            *(float2*)&g_h[o] = make_float2(
                rnef(v0 * (u0 / (1.0f + __expf(-u0)))),
                rnef(v1 * (u1 / (1.0f + __expf(-u1)))));
            float u2 = acc1[mi][ni][2], u3 = acc1[mi][ni][3];
            float v2 = acc3[mi][ni][2], v3 = acc3[mi][ni][3];
            *(float2*)&g_h[o + (size_t)8*FFN] = make_float2(
                rnef(v2 * (u2 / (1.0f + __expf(-u2)))),
                rnef(v3 * (u3 / (1.0f + __expf(-u3)))));
        }
    }
}

// ---------------- GEMM2: y = H@W2^T ----------------
// 288 threads: 8 consumer warps (warp tile 64x64, 2M x 4N over 128x256 CTA tile).
__global__ void __launch_bounds__(288, 1)
gemm2_k(const __grid_constant__ CUtensorMap a_map,
        const __grid_constant__ CUtensorMap b_map)
{
    const int e = blockIdx.z;
    const int cnt = g_counts[e];
    const int m0 = blockIdx.x * BM;
    if (m0 >= cnt) return;
    const int base = g_base[e];
    const int n0 = blockIdx.y * BN2;

    extern __shared__ __align__(1024) char smem[];
    const uint32_t sb = smem_u32(smem);
    const int tid = threadIdx.x, wid = tid >> 5, lane = tid & 31;

    if (tid == 0) {
        #pragma unroll
        for (int s = 0; s < ST; s++) { MBAR_INIT(sb+FULL_OFF(s), 1); MBAR_INIT(sb+EMPTY_OFF(s), 8); }
    }
    __syncthreads();

    if (wid == 8) {                 // producer
        int s = 0, ph = 1;
        #pragma unroll 1
        for (int kt = 0; kt < KT2; kt++) {
            MBAR_WAIT(sb+EMPTY_OFF(s), ph);
            if (elect_one()) {
                MBAR_EXPECT_TX(sb+FULL_OFF(s), SM2_STAGE);
                tma2d(sb+SM2_A(s), &a_map, kt*BK, base + m0,  sb+FULL_OFF(s));
                tma2d(sb+SM2_B(s), &b_map, kt*BK, e*DIM + n0, sb+FULL_OFF(s));
            }
            if (++s == ST) { s = 0; ph ^= 1; }
        }
        return;
    }

    // consumer: warp tile 64(M) x 64(N)
    const int wm = (wid & 1) * 64, wn = (wid >> 1) * 64;
    const int g = lane >> 2, tg = lane & 3;
    const uint32_t mk = (uint32_t)g << 4;

    uint32_t aRow[8], bRow[8], cofs[4][2];
    #pragma unroll
    for (int i = 0; i < 8; i++) aRow[i] = (uint32_t)(wm + g + i*8) * 128;
    #pragma unroll
    for (int i = 0; i < 8; i++) bRow[i] = (uint32_t)(wn + i*8 + g) * 128;
    #pragma unroll
    for (int kk = 0; kk < 4; kk++) {
        cofs[kk][0] = ((uint32_t)(kk*8 + tg)     * 4) ^ mk;
        cofs[kk][1] = ((uint32_t)(kk*8 + tg + 4) * 4) ^ mk;
    }

    float acc[4][8][4] = {};
    int s = 0, ph = 0;
    #pragma unroll 1
    for (int kt = 0; kt < KT2; kt++) {
        MBAR_WAIT(sb+FULL_OFF(s), ph);
        const uint32_t At = sb + SM2_A(s), Bt = sb + SM2_B(s);
        #pragma unroll
        for (int kk = 0; kk < 4; kk++) {
            uint32_t a[4][4];
            #pragma unroll
            for (int mi = 0; mi < 4; mi++) {
                a[mi][0] = lds_u32(At + aRow[2*mi]   + cofs[kk][0]);
                a[mi][1] = lds_u32(At + aRow[2*mi+1] + cofs[kk][0]);
                a[mi][2] = lds_u32(At + aRow[2*mi]   + cofs[kk][1]);
                a[mi][3] = lds_u32(At + aRow[2*mi+1] + cofs[kk][1]);
            }
            #pragma unroll
            for (int ni = 0; ni < 8; ni++) {
                uint32_t bf[2];
                bf[0] = tf32_bits(lds_f32(Bt + bRow[ni] + cofs[kk][0]));
                bf[1] = tf32_bits(lds_f32(Bt + bRow[ni] + cofs[kk][1]));
                #pragma unroll
                for (int mi = 0; mi < 4; mi++) mma_tf32(acc[mi][ni], a[mi], bf);
            }
        }
        __syncwarp();
        if (lane == 0) MBAR_ARRIVE(sb+EMPTY_OFF(s));
        if (++s == ST) { s = 0; ph ^= 1; }
    }

    #pragma unroll
    for (int mi = 0; mi < 4; mi++) {
        #pragma unroll
        for (int ni = 0; ni < 8; ni++) {
            int row = base + m0 + wm + mi*16 + g;
            int col = n0 + wn + ni*8 + tg*2;
            size_t o = (size_t)row*DIM + col;
            *(float2*)&g_y[o]                 = make_float2(acc[mi][ni][0], acc[mi][ni][1]);
            *(float2*)&g_y[o + (size_t)8*DIM] = make_float2(acc[mi][ni][2], acc[mi][ni][3]);
        }
    }
}

// ---------------- final gather ----------------
__global__ void gather_k(const int* __restrict__ map, const float* __restrict__ probs,
                         float* __restrict__ out) {
    const int t = blockIdx.x, tid = threadIdx.x;
    float4 acc0 = make_float4(0.f, 0.f, 0.f, 0.f);
    float4 acc1 = make_float4(0.f, 0.f, 0.f, 0.f);
    #pragma unroll
    for (int e = 0; e < NE; e++) {
        if (map[t*NE + e]) {
            float p = probs[t*NE + e];
            int row = g_base[e] + g_slot_of[t*NE + e];
            const float4* yr = (const float4*)(g_y + (size_t)row*DIM);
            float4 y0 = yr[tid], y1 = yr[tid + 256];
            acc0.x += p*y0.x; acc0.y += p*y0.y; acc0.z += p*y0.z; acc0.w += p*y0.w;
            acc1.x += p*y1.x; acc1.y += p*y1.y; acc1.z += p*y1.z; acc1.w += p*y1.w;
        }
    }
    float4* o = (float4*)(out + (size_t)t*DIM);
    o[tid]       = acc0;
    o[tid + 256] = acc1;
}

// ---------------- host ----------------
typedef CUresult (*EncodeFn)(CUtensorMap*, CUtensorMapDataType, cuuint32_t, void*,
                             const cuuint64_t*, const cuuint64_t*, const cuuint32_t*,
                             const cuuint32_t*, CUtensorMapInterleave, CUtensorMapSwizzle,
                             CUtensorMapL2promotion, CUtensorMapFloatOOBfill);

static void make_map(EncodeFn enc, CUtensorMap* m, void* base,
                     uint64_t d0, uint64_t d1, uint32_t b0, uint32_t b1) {
    cuuint64_t dims[2] = {d0, d1};
    cuuint64_t strides[1] = {d0 * 4};
    cuuint32_t box[2] = {b0, b1};
    cuuint32_t es[2] = {1, 1};
    enc(m, CU_TENSOR_MAP_DATA_TYPE_FLOAT32, 2, base, dims, strides, box, es,
        CU_TENSOR_MAP_INTERLEAVE_NONE, CU_TENSOR_MAP_SWIZZLE_128B,
        CU_TENSOR_MAP_L2_PROMOTION_L2_128B, CU_TENSOR_MAP_FLOAT_OOB_FILL_NONE);
}

extern "C" void kernel_launch(void* const* d_in, const int* in_sizes, int n_in,
                              void* d_out, int out_size) {
    const float* x     = (const float*)d_in[0];
    const int*   map   = (const int*)  d_in[1];
    const float* probs = (const float*)d_in[2];
    const float* w1    = (const float*)d_in[3];
    const float* w2    = (const float*)d_in[4];
    const float* w3    = (const float*)d_in[5];
    float*       out   = (float*)d_out;

    void *p_xp, *p_h;
    cudaGetSymbolAddress(&p_xp, g_xp);
    cudaGetSymbolAddress(&p_h,  g_h);

    EncodeFn enc = nullptr;
    cudaDriverEntryPointQueryResult qr;
    cudaGetDriverEntryPointByVersion("cuTensorMapEncodeTiled", (void**)&enc, 12000,
                                     cudaEnableDefault, &qr);

    CUtensorMap mA1, mB1, mB3, mA2, mB2;
    make_map(enc, &mA1, p_xp,       DIM, NROWS,            BK, BM);
    make_map(enc, &mB1, (void*)w1,  DIM, (uint64_t)NE*FFN, BK, BN1);
    make_map(enc, &mB3, (void*)w3,  DIM, (uint64_t)NE*FFN, BK, BN1);
    make_map(enc, &mA2, p_h,        FFN, NROWS,            BK, BM);
    make_map(enc, &mB2, (void*)w2,  FFN, (uint64_t)NE*DIM, BK, BN2);

    cudaFuncSetAttribute(gemm1_k, cudaFuncAttributeMaxDynamicSharedMemorySize, SM_TOTAL);
    cudaFuncSetAttribute(gemm2_k, cudaFuncAttributeMaxDynamicSharedMemorySize, SM_TOTAL);

    route_all_k<<<1, 1024>>>(map);
    permute_round_k<<<NT, 256>>>(x, map);
    gemm1_k<<<dim3(NT/BM, FFN/BN1, NE), 288, SM_TOTAL>>>(mA1, mB1, mB3);
    gemm2_k<<<dim3(NT/BM, DIM/BN2, NE), 288, SM_TOTAL>>>(mA2, mB2);
    gather_k<<<NT, 256>>>(map, probs, out);
}